// round 14
// baseline (speedup 1.0000x reference)
#include <cuda_runtime.h>
#include <cuda_bf16.h>
#include <math.h>
#include <float.h>
#include <stdint.h>

#define B 4
#define T 2048
#define D 512
#define NT1 (T / 128)                  // 16 tiles per side
#define NTRI1 (NT1 * (NT1 + 1) / 2)    // 136 lower-tri tiles

// ---------------- scratch (static device memory; no allocation) ----------------
__device__ __nv_bfloat16 g_xhi[(size_t)B * T * D];   // 8 MB
__device__ __nv_bfloat16 g_xlo[(size_t)B * T * D];   // 8 MB
__device__ float g_sim[(size_t)B * T * T];           // 64 MB
__device__ float g_h[2][(size_t)B * T * D];          // 32 MB
__device__ int   g_top_idx[(size_t)B * T * 16];
__device__ int   g_top_cnt[(size_t)B * T];
__device__ int   g_con_idx[(size_t)B * T * 8];
__device__ int   g_con_cnt[(size_t)B * T];

__device__ __forceinline__ float sigmoidf_(float v) { return 1.0f / (1.0f + expf(-v)); }
__device__ __forceinline__ float softplusf_(float v) {
    return (v > 20.0f) ? v : log1pf(expf(v));
}

__device__ __forceinline__ uint32_t smem_u32(const void* p) {
    uint32_t a;
    asm("{ .reg .u64 t; cvta.to.shared.u64 t, %1; cvt.u32.u64 %0, t; }"
        : "=r"(a) : "l"(p));
    return a;
}
__device__ __forceinline__ void cp_async16(uint32_t dst, const void* src) {
    asm volatile("cp.async.cg.shared.global [%0], [%1], 16;"
                 :: "r"(dst), "l"(src) : "memory");
}
__device__ __forceinline__ void cp_commit() {
    asm volatile("cp.async.commit_group;" ::: "memory");
}
__device__ __forceinline__ void cp_wait1() {
    asm volatile("cp.async.wait_group 1;" ::: "memory");
}
__device__ __forceinline__ void cp_wait0() {
    asm volatile("cp.async.wait_group 0;" ::: "memory");
}
__device__ __forceinline__ void mma16816(float* c, const uint32_t* a, const uint32_t* b) {
    asm volatile(
        "mma.sync.aligned.m16n8k16.row.col.f32.bf16.bf16.f32 "
        "{%0,%1,%2,%3}, {%4,%5,%6,%7}, {%8,%9}, {%0,%1,%2,%3};"
        : "+f"(c[0]), "+f"(c[1]), "+f"(c[2]), "+f"(c[3])
        : "r"(a[0]), "r"(a[1]), "r"(a[2]), "r"(a[3]), "r"(b[0]), "r"(b[1]));
}
__device__ __forceinline__ void ldm_x4(uint32_t* r, uint32_t addr) {
    asm volatile("ldmatrix.sync.aligned.m8n8.x4.shared.b16 {%0,%1,%2,%3}, [%4];"
                 : "=r"(r[0]), "=r"(r[1]), "=r"(r[2]), "=r"(r[3]) : "r"(addr));
}

__device__ __forceinline__ void split_row_elem(float v, __nv_bfloat16* hi,
                                               __nv_bfloat16* lo) {
    *hi = __float2bfloat16(v);
    *lo = __float2bfloat16(v - __bfloat162float(*hi));
}

// key transform: monotonic u32 (bigger key == bigger float)
__device__ __forceinline__ uint32_t fkey(float f) {
    unsigned u = __float_as_uint(f);
    return (u & 0x80000000u) ? ~u : (u | 0x80000000u);
}

// ---------------- kernel 1: row-normalize x -> bf16 hi/lo split (round 0 only) --
__global__ void norm_kernel(const float* __restrict__ hext) {
    int row = blockIdx.x;
    const float* h = hext + (size_t)row * D;
    int tid = threadIdx.x;           // 128 threads
    float4 v = ((const float4*)h)[tid];
    float ss = v.x * v.x + v.y * v.y + v.z * v.z + v.w * v.w;
    #pragma unroll
    for (int off = 16; off; off >>= 1) ss += __shfl_down_sync(0xffffffffu, ss, off);
    __shared__ float w[4];
    if ((tid & 31) == 0) w[tid >> 5] = ss;
    __syncthreads();
    float tot = w[0] + w[1] + w[2] + w[3];
    float rinv = 1.0f / fmaxf(sqrtf(tot), 1e-12f);
    float vv[4] = {v.x * rinv, v.y * rinv, v.z * rinv, v.w * rinv};
    __nv_bfloat16 hi[4], lo[4];
    #pragma unroll
    for (int c = 0; c < 4; c++) split_row_elem(vv[c], &hi[c], &lo[c]);
    *(uint2*)&g_xhi[(size_t)row * D + tid * 4] = *(uint2*)hi;
    *(uint2*)&g_xlo[(size_t)row * D + tid * 4] = *(uint2*)lo;
}

// ---------------- kernel 2: sim GEMM, ldmatrix + 3-stage cp.async pipeline ------
#define STG_B 16384                      // 4 tiles x 4096 B
#define TILE32 4096

__global__ void __launch_bounds__(256, 2) sim_mma_kernel() {
    __shared__ __align__(128) char smem[3 * STG_B];   // 48 KB static
    uint32_t sbase = smem_u32(smem);
    int tid = threadIdx.x;
    int lane = tid & 31, warp = tid >> 5;
    int wm = warp >> 2;                  // 0..1 (M)
    int wn = warp & 3;                   // 0..3 (N)
    int grp = lane >> 2;                 // 0..7
    int tig = lane & 3;                  // 0..3

    int blk = blockIdx.x;
    int b = blk / NTRI1;
    int q = blk % NTRI1;
    int i = 0;
    while ((i + 1) * (i + 2) / 2 <= q) i++;
    int j = q - i * (i + 1) / 2;

    const __nv_bfloat16* Xhi = g_xhi + (size_t)b * T * D;
    const __nv_bfloat16* Xlo = g_xlo + (size_t)b * T * D;
    const __nv_bfloat16* srcs[4] = {
        Xhi + (size_t)(i * 128) * D,     // Ahi
        Xlo + (size_t)(i * 128) * D,     // Alo
        Xhi + (size_t)(j * 128) * D,     // Bhi
        Xlo + (size_t)(j * 128) * D      // Blo
    };

    uint32_t pdst[4];
    const __nv_bfloat16* psrc[4];
    #pragma unroll
    for (int uu = 0; uu < 4; uu++) {
        int u = tid + uu * 256;
        int tt = u >> 8, rr = (u >> 1) & 127, hh = u & 1;
        pdst[uu] = tt * TILE32 + ((rr * 32 + hh * 16) ^ ((rr & 4) << 2));
        psrc[uu] = srcs[tt] + (size_t)rr * D + hh * 8;
    }

    uint32_t laneoff = (uint32_t)(((lane & 15) * 32 + (lane >> 4) * 16) ^
                                  (((lane & 15) & 4) << 2));
    uint32_t aoff = (uint32_t)(wm * 64 * 32) + laneoff;
    uint32_t boff = (uint32_t)(wn * 32 * 32) + laneoff;

    float acc[4][4][4];
    #pragma unroll
    for (int am = 0; am < 4; am++)
        #pragma unroll
        for (int an = 0; an < 4; an++)
            #pragma unroll
            for (int c = 0; c < 4; c++) acc[am][an][c] = 0.0f;

    const int NC = D / 16;               // 32 chunks of K=16

    #pragma unroll
    for (int pc = 0; pc < 2; pc++) {
        #pragma unroll
        for (int uu = 0; uu < 4; uu++)
            cp_async16(sbase + pc * STG_B + pdst[uu], psrc[uu] + pc * 16);
        cp_commit();
    }

    for (int c = 0; c < NC; c++) {
        if (c < NC - 1) cp_wait1(); else cp_wait0();
        __syncthreads();
        if (c + 2 < NC) {
            uint32_t stb = sbase + ((c + 2) % 3) * STG_B;
            int k0 = (c + 2) * 16;
            #pragma unroll
            for (int uu = 0; uu < 4; uu++)
                cp_async16(stb + pdst[uu], psrc[uu] + k0);
            cp_commit();
        }

        uint32_t stb = sbase + (c % 3) * STG_B;
        uint32_t bhi[4][2], blo[4][2];
        #pragma unroll
        for (int p = 0; p < 2; p++) {
            uint32_t r[4];
            ldm_x4(r, stb + 2 * TILE32 + boff + p * 512);
            bhi[2 * p][0] = r[0]; bhi[2 * p + 1][0] = r[1];
            bhi[2 * p][1] = r[2]; bhi[2 * p + 1][1] = r[3];
            ldm_x4(r, stb + 3 * TILE32 + boff + p * 512);
            blo[2 * p][0] = r[0]; blo[2 * p + 1][0] = r[1];
            blo[2 * p][1] = r[2]; blo[2 * p + 1][1] = r[3];
        }
        #pragma unroll
        for (int am = 0; am < 4; am++) {
            uint32_t ah[4], al[4];
            ldm_x4(ah, stb + aoff + am * 512);
            ldm_x4(al, stb + TILE32 + aoff + am * 512);
            #pragma unroll
            for (int an = 0; an < 4; an++) {
                mma16816(acc[am][an], ah, bhi[an]);
                mma16816(acc[am][an], ah, blo[an]);
                mma16816(acc[am][an], al, bhi[an]);
            }
        }
    }

    #pragma unroll
    for (int am = 0; am < 4; am++) {
        int row0 = i * 128 + wm * 64 + am * 16 + grp;
        #pragma unroll
        for (int an = 0; an < 4; an++) {
            int col = j * 128 + wn * 32 + an * 8 + tig * 2;
            float* d0 = &g_sim[((size_t)(b * T + row0)) * T + col];
            float* d1 = &g_sim[((size_t)(b * T + row0 + 8)) * T + col];
            *(float2*)d0 = make_float2(acc[am][an][0], acc[am][an][1]);
            *(float2*)d1 = make_float2(acc[am][an][2], acc[am][an][3]);
        }
    }
}

// ---------------- kernel 3: per-row top-k via 2-level radix select -------------
__device__ __forceinline__ void suffix_thresh(const uint32_t* hist, int k,
                                              uint32_t* wsum, int* sh_thr,
                                              int tid, int lane, int wrp) {
    uint32_t h0 = hist[tid];
    uint32_t v = h0;
    #pragma unroll
    for (int off = 1; off < 32; off <<= 1) {
        uint32_t o = __shfl_down_sync(0xffffffffu, v, off);
        if (lane + off < 32) v += o;
    }
    if (lane == 0) wsum[wrp] = v;
    __syncthreads();
    uint32_t exc = 0;
    for (int w2 = wrp + 1; w2 < 8; w2++) exc += wsum[w2];
    uint32_t sfx = v + exc;
    if (sfx >= (uint32_t)k && sfx - h0 < (uint32_t)k) *sh_thr = tid;
    __syncthreads();
}

__global__ void __launch_bounds__(256) topk_kernel(int eff_sim, int eff_con) {
    int row = blockIdx.x;
    int t = row & (T - 1);
    int n = t;
    int tid = threadIdx.x;
    int lane = tid & 31, wrp = tid >> 5;

    __shared__ uint32_t vals[T];
    __shared__ uint32_t hist[256];
    __shared__ uint32_t wsum[8];
    __shared__ unsigned long long wred[8];
    __shared__ uint32_t wred32[8];
    __shared__ int sh_thr;
    __shared__ uint32_t sh_win;
    __shared__ int nsel, nc1, nc2;
    __shared__ int sel[16];
    __shared__ uint16_t cand1[T];
    __shared__ uint32_t cand2[T];

    const float* srow = &g_sim[(size_t)row * T];
    int ksel = min(eff_sim, n);
    if (tid == 0) { nsel = 0; nc1 = 0; nc2 = 0; }
    hist[tid] = 0;
    __syncthreads();

    // pass 1: float4 load + transform + hist
    int n4 = n >> 2;
    for (int s4 = tid; s4 < n4; s4 += 256) {
        float4 f = ((const float4*)srow)[s4];
        uint32_t k0 = fkey(f.x), k1 = fkey(f.y), k2 = fkey(f.z), k3 = fkey(f.w);
        ((uint4*)vals)[s4] = make_uint4(k0, k1, k2, k3);
        if (ksel > 0) {
            atomicAdd(&hist[k0 >> 24], 1u);
            atomicAdd(&hist[k1 >> 24], 1u);
            atomicAdd(&hist[k2 >> 24], 1u);
            atomicAdd(&hist[k3 >> 24], 1u);
        }
    }
    for (int s = n4 * 4 + tid; s < n; s += 256) {
        uint32_t k0 = fkey(srow[s]);
        vals[s] = k0;
        if (ksel > 0) atomicAdd(&hist[k0 >> 24], 1u);
    }
    __syncthreads();

    if (ksel > 0) {
        suffix_thresh(hist, ksel, wsum, &sh_thr, tid, lane, wrp);
        uint32_t b3 = (uint32_t)sh_thr;
        // pass 2: classify (uint4 reads from smem)
        for (int s4 = tid; s4 < n4; s4 += 256) {
            uint4 v = ((const uint4*)vals)[s4];
            int s = s4 * 4;
            uint32_t bb;
            bb = v.x >> 24;
            if (bb > b3) sel[atomicAdd(&nsel, 1) & 15] = s;
            else if (bb == b3) cand1[atomicAdd(&nc1, 1)] = (uint16_t)s;
            bb = v.y >> 24;
            if (bb > b3) sel[atomicAdd(&nsel, 1) & 15] = s + 1;
            else if (bb == b3) cand1[atomicAdd(&nc1, 1)] = (uint16_t)(s + 1);
            bb = v.z >> 24;
            if (bb > b3) sel[atomicAdd(&nsel, 1) & 15] = s + 2;
            else if (bb == b3) cand1[atomicAdd(&nc1, 1)] = (uint16_t)(s + 2);
            bb = v.w >> 24;
            if (bb > b3) sel[atomicAdd(&nsel, 1) & 15] = s + 3;
            else if (bb == b3) cand1[atomicAdd(&nc1, 1)] = (uint16_t)(s + 3);
        }
        for (int s = n4 * 4 + tid; s < n; s += 256) {
            uint32_t bb = vals[s] >> 24;
            if (bb > b3) sel[atomicAdd(&nsel, 1) & 15] = s;
            else if (bb == b3) cand1[atomicAdd(&nc1, 1)] = (uint16_t)s;
        }
        __syncthreads();

        int kneed2 = ksel - nsel;
        if (kneed2 > 0) {
            hist[tid] = 0;
            __syncthreads();
            int m1 = nc1;
            for (int q2 = tid; q2 < m1; q2 += 256)
                atomicAdd(&hist[(vals[cand1[q2]] >> 16) & 0xFFu], 1u);
            __syncthreads();
            suffix_thresh(hist, kneed2, wsum, &sh_thr, tid, lane, wrp);
            uint32_t b2 = (uint32_t)sh_thr;
            for (int q2 = tid; q2 < m1; q2 += 256) {
                int s = cand1[q2];
                uint32_t bb = (vals[s] >> 16) & 0xFFu;
                if (bb > b2) sel[atomicAdd(&nsel, 1) & 15] = s;
                else if (bb == b2)
                    cand2[atomicAdd(&nc2, 1)] =
                        ((vals[s] & 0xFFFFu) << 11) | (uint32_t)(2047 - s);
            }
            __syncthreads();

            int base = nsel;
            int kt = ksel - base;
            int m2 = nc2;
            for (int it = 0; it < kt; it++) {
                uint32_t best = 0;
                for (int q2 = tid; q2 < m2; q2 += 256)
                    best = max(best, cand2[q2]);
                #pragma unroll
                for (int off = 16; off; off >>= 1)
                    best = max(best, __shfl_down_sync(0xffffffffu, best, off));
                if (lane == 0) wred32[wrp] = best;
                __syncthreads();
                if (wrp == 0) {
                    uint32_t bb = (lane < 8) ? wred32[lane] : 0u;
                    #pragma unroll
                    for (int off = 4; off; off >>= 1)
                        bb = max(bb, __shfl_down_sync(0xffffffffu, bb, off));
                    if (lane == 0) sh_win = bb;
                }
                __syncthreads();
                uint32_t wkey = sh_win;
                if (tid == 0 && base + it < 16)
                    sel[base + it] = 2047 - (int)(wkey & 0x7FFu);
                for (int q2 = tid; q2 < m2; q2 += 256)
                    if (cand2[q2] == wkey) cand2[q2] = 0;
                __syncthreads();
            }
            if (tid == 0) nsel = ksel;
        }
    }
    __syncthreads();
    if (tid < ksel) g_top_idx[(size_t)row * 16 + tid] = sel[tid];
    if (tid == 0) g_top_cnt[row] = ksel;

    int m = eff_con - (T - t);
    int mm = 0;
    if (m > 0) {
        mm = min(m, n - ksel);
        if (tid < ksel) vals[sel[tid]] = 0xFFFFFFFFu;
        __syncthreads();
        for (int it = 0; it < mm; it++) {
            unsigned long long best = 0xFFFFFFFFFFFFFFFFull;
            for (int s = tid; s < n; s += 256) {
                unsigned long long key =
                    ((unsigned long long)vals[s] << 32) | (unsigned)s;
                if (key < best) best = key;
            }
            #pragma unroll
            for (int off = 16; off; off >>= 1) {
                unsigned long long o = __shfl_down_sync(0xffffffffu, best, off);
                if (o < best) best = o;
            }
            if (lane == 0) wred[wrp] = best;
            __syncthreads();
            if (wrp == 0) {
                unsigned long long bb =
                    (lane < 8) ? wred[lane] : 0xFFFFFFFFFFFFFFFFull;
                #pragma unroll
                for (int off = 4; off; off >>= 1) {
                    unsigned long long o = __shfl_down_sync(0xffffffffu, bb, off);
                    if (o < bb) bb = o;
                }
                if (lane == 0) {
                    int idx = (int)(unsigned)bb;
                    g_con_idx[(size_t)row * 8 + it] = idx;
                    vals[idx] = 0xFFFFFFFFu;
                }
            }
            __syncthreads();
        }
    }
    if (tid == 0) g_con_cnt[row] = mm;
}

// ---------------- kernel 4: aggregate, 2 rows per 256-thread block --------------
__global__ void __launch_bounds__(256) agg_kernel(
    const float* __restrict__ hext, int in_buf, int out_buf,
    const float* __restrict__ gain, const float* __restrict__ bias,
    const float* __restrict__ lmix, const float* __restrict__ lalpha,
    const float* __restrict__ lmom, const float* __restrict__ lscale,
    int r, int final_round, int write_xn,
    const float* __restrict__ x, float* __restrict__ out) {

    int sub = threadIdx.x >> 7;          // 0..1
    int d = threadIdx.x & 127;
    int row = blockIdx.x * 2 + sub;
    int b = row >> 11;
    const float* hbase = (in_buf < 0) ? hext : &g_h[in_buf][0];
    const float4* h4 = (const float4*)hbase;

    __shared__ int sidx[2][16];
    __shared__ int scidx[2][8];
    __shared__ int scnt[2][2];
    __shared__ float wnorm[2][4];
    if (d == 0) { scnt[sub][0] = g_top_cnt[row]; scnt[sub][1] = g_con_cnt[row]; }
    if (d < 16) sidx[sub][d] = g_top_idx[(size_t)row * 16 + d];
    if (d < 8)  scidx[sub][d] = g_con_idx[(size_t)row * 8 + d];
    __syncthreads();
    int cp = scnt[sub][0], cc = scnt[sub][1];

    float mix   = sigmoidf_(lmix[r]);
    float alpha = sigmoidf_(lalpha[r]);
    float mom   = sigmoidf_(lmom[0]);
    float scale = softplusf_(lscale[0]) + 0.01f;
    float invp = 1.0f / fmaxf((float)cp, 1.0f);
    float invc = 1.0f / fmaxf((float)cc, 1.0f);

    size_t bT = (size_t)b * T;
    const int DQ = D / 4;

    float4 sp = make_float4(0.f, 0.f, 0.f, 0.f);
    float4 sc = make_float4(0.f, 0.f, 0.f, 0.f);
    for (int i = 0; i < cp; i++) {
        float4 v = h4[(bT + sidx[sub][i]) * DQ + d];
        sp.x += v.x; sp.y += v.y; sp.z += v.z; sp.w += v.w;
    }
    for (int i = 0; i < cc; i++) {
        float4 v = h4[(bT + scidx[sub][i]) * DQ + d];
        sc.x += v.x; sc.y += v.y; sc.z += v.z; sc.w += v.w;
    }
    float4 hv = h4[(size_t)row * DQ + d];
    float4 gr = ((const float4*)(gain + (size_t)r * D))[d];
    float4 br = ((const float4*)(bias + (size_t)r * D))[d];

    float hn[4], hvv[4] = {hv.x, hv.y, hv.z, hv.w};
    float spp[4] = {sp.x, sp.y, sp.z, sp.w};
    float scc[4] = {sc.x, sc.y, sc.z, sc.w};
    float grr[4] = {gr.x, gr.y, gr.z, gr.w};
    float brr[4] = {br.x, br.y, br.z, br.w};
    #pragma unroll
    for (int c = 0; c < 4; c++) {
        float ctx = alpha * (spp[c] * invp) + (1.0f - alpha) * (scc[c] * invc);
        float blended = mix * hvv[c] + (1.0f - mix) * ctx;
        float z = blended * grr[c] + brr[c];
        float g = 0.5f * z * (1.0f + erff(z * 0.70710678118654752f));
        hn[c] = mom * hvv[c] + (1.0f - mom) * g;
    }
    float4 ho = make_float4(hn[0], hn[1], hn[2], hn[3]);
    ((float4*)(&g_h[out_buf][0]))[(size_t)row * DQ + d] = ho;
    if (final_round) {
        float4 xv = ((const float4*)x)[(size_t)row * DQ + d];
        float4 ov = make_float4((hn[0] - xv.x) * scale, (hn[1] - xv.y) * scale,
                                (hn[2] - xv.z) * scale, (hn[3] - xv.w) * scale);
        ((float4*)out)[(size_t)row * DQ + d] = ov;
    }
    if (write_xn) {
        float ss = hn[0] * hn[0] + hn[1] * hn[1] + hn[2] * hn[2] + hn[3] * hn[3];
        #pragma unroll
        for (int off = 16; off; off >>= 1)
            ss += __shfl_down_sync(0xffffffffu, ss, off);
        if ((d & 31) == 0) wnorm[sub][(d >> 5)] = ss;
        __syncthreads();
        float tot = wnorm[sub][0] + wnorm[sub][1] + wnorm[sub][2] + wnorm[sub][3];
        float rinv = 1.0f / fmaxf(sqrtf(tot), 1e-12f);
        __nv_bfloat16 hi[4], lo[4];
        #pragma unroll
        for (int c = 0; c < 4; c++) split_row_elem(hn[c] * rinv, &hi[c], &lo[c]);
        *(uint2*)&g_xhi[(size_t)row * D + d * 4] = *(uint2*)hi;
        *(uint2*)&g_xlo[(size_t)row * D + d * 4] = *(uint2*)lo;
    }
}

// ---------------- launch (kernel launches ONLY; no host API calls) --------------
extern "C" void kernel_launch(void* const* d_in, const int* in_sizes, int n_in,
                              void* d_out, int out_size) {
    const float* x      = (const float*)d_in[0];
    const float* gain   = (const float*)d_in[1];
    const float* bias   = (const float*)d_in[2];
    const float* lmix   = (const float*)d_in[3];
    const float* lalpha = (const float*)d_in[4];
    const float* lmom   = (const float*)d_in[5];
    const float* lscale = (const float*)d_in[6];
    float* out = (float*)d_out;

    static const int KS[3] = {4, 8, 16};
    static const int KC[3] = {2, 4, 8};

    norm_kernel<<<B * T, 128>>>(x);      // round-0 normalize from x
    int inb = -1, outb = 0;
    for (int r = 0; r < 3; r++) {
        sim_mma_kernel<<<B * NTRI1, 256>>>();
        topk_kernel<<<B * T, 256>>>(KS[r], KC[r]);
        agg_kernel<<<B * T / 2, 256>>>(x, inb, outb, gain, bias, lmix, lalpha,
                                       lmom, lscale, r, (r == 2) ? 1 : 0,
                                       (r < 2) ? 1 : 0, x, out);
        inb = outb;
        outb ^= 1;
    }
}

// round 15
// speedup vs baseline: 1.0236x; 1.0236x over previous
#include <cuda_runtime.h>
#include <cuda_bf16.h>
#include <math.h>
#include <float.h>
#include <stdint.h>

#define B 4
#define T 2048
#define D 512
#define NT1 (T / 128)                  // 16 tiles per side
#define NTRI1 (NT1 * (NT1 + 1) / 2)    // 136 lower-tri tiles

// ---------------- scratch (static device memory; no allocation) ----------------
__device__ __nv_bfloat16 g_xhi[(size_t)B * T * D];   // 8 MB
__device__ __nv_bfloat16 g_xlo[(size_t)B * T * D];   // 8 MB
__device__ float g_sim[(size_t)B * T * T];           // 64 MB
__device__ float g_h[2][(size_t)B * T * D];          // 32 MB
__device__ int   g_top_idx[(size_t)B * T * 16];
__device__ int   g_top_cnt[(size_t)B * T];
__device__ int   g_con_idx[(size_t)B * T * 8];
__device__ int   g_con_cnt[(size_t)B * T];

__device__ __forceinline__ float sigmoidf_(float v) { return 1.0f / (1.0f + expf(-v)); }
__device__ __forceinline__ float softplusf_(float v) {
    return (v > 20.0f) ? v : log1pf(expf(v));
}

__device__ __forceinline__ uint32_t smem_u32(const void* p) {
    uint32_t a;
    asm("{ .reg .u64 t; cvta.to.shared.u64 t, %1; cvt.u32.u64 %0, t; }"
        : "=r"(a) : "l"(p));
    return a;
}
__device__ __forceinline__ void cp_async16(uint32_t dst, const void* src) {
    asm volatile("cp.async.cg.shared.global [%0], [%1], 16;"
                 :: "r"(dst), "l"(src) : "memory");
}
__device__ __forceinline__ void cp_commit() {
    asm volatile("cp.async.commit_group;" ::: "memory");
}
__device__ __forceinline__ void cp_wait1() {
    asm volatile("cp.async.wait_group 1;" ::: "memory");
}
__device__ __forceinline__ void cp_wait0() {
    asm volatile("cp.async.wait_group 0;" ::: "memory");
}
__device__ __forceinline__ void mma16816(float* c, const uint32_t* a, const uint32_t* b) {
    asm volatile(
        "mma.sync.aligned.m16n8k16.row.col.f32.bf16.bf16.f32 "
        "{%0,%1,%2,%3}, {%4,%5,%6,%7}, {%8,%9}, {%0,%1,%2,%3};"
        : "+f"(c[0]), "+f"(c[1]), "+f"(c[2]), "+f"(c[3])
        : "r"(a[0]), "r"(a[1]), "r"(a[2]), "r"(a[3]), "r"(b[0]), "r"(b[1]));
}
__device__ __forceinline__ void ldm_x4(uint32_t* r, uint32_t addr) {
    asm volatile("ldmatrix.sync.aligned.m8n8.x4.shared.b16 {%0,%1,%2,%3}, [%4];"
                 : "=r"(r[0]), "=r"(r[1]), "=r"(r[2]), "=r"(r[3]) : "r"(addr));
}

__device__ __forceinline__ void split_row_elem(float v, __nv_bfloat16* hi,
                                               __nv_bfloat16* lo) {
    *hi = __float2bfloat16(v);
    *lo = __float2bfloat16(v - __bfloat162float(*hi));
}

// key transform: monotonic u32 (bigger key == bigger float)
__device__ __forceinline__ uint32_t fkey(float f) {
    unsigned u = __float_as_uint(f);
    return (u & 0x80000000u) ? ~u : (u | 0x80000000u);
}

// ---------------- kernel 1: row-normalize x -> bf16 hi/lo split (round 0 only) --
__global__ void norm_kernel(const float* __restrict__ hext) {
    int row = blockIdx.x;
    const float* h = hext + (size_t)row * D;
    int tid = threadIdx.x;           // 128 threads
    float4 v = ((const float4*)h)[tid];
    float ss = v.x * v.x + v.y * v.y + v.z * v.z + v.w * v.w;
    #pragma unroll
    for (int off = 16; off; off >>= 1) ss += __shfl_down_sync(0xffffffffu, ss, off);
    __shared__ float w[4];
    if ((tid & 31) == 0) w[tid >> 5] = ss;
    __syncthreads();
    float tot = w[0] + w[1] + w[2] + w[3];
    float rinv = 1.0f / fmaxf(sqrtf(tot), 1e-12f);
    float vv[4] = {v.x * rinv, v.y * rinv, v.z * rinv, v.w * rinv};
    __nv_bfloat16 hi[4], lo[4];
    #pragma unroll
    for (int c = 0; c < 4; c++) split_row_elem(vv[c], &hi[c], &lo[c]);
    *(uint2*)&g_xhi[(size_t)row * D + tid * 4] = *(uint2*)hi;
    *(uint2*)&g_xlo[(size_t)row * D + tid * 4] = *(uint2*)lo;
}

// ---------------- kernel 2: sim GEMM, ldmatrix + 3-stage cp.async pipeline ------
#define STG_B 16384                      // 4 tiles x 4096 B
#define TILE32 4096

__global__ void __launch_bounds__(256, 2) sim_mma_kernel() {
    __shared__ __align__(128) char smem[3 * STG_B];   // 48 KB static
    uint32_t sbase = smem_u32(smem);
    int tid = threadIdx.x;
    int lane = tid & 31, warp = tid >> 5;
    int wm = warp >> 2;                  // 0..1 (M)
    int wn = warp & 3;                   // 0..3 (N)
    int grp = lane >> 2;                 // 0..7
    int tig = lane & 3;                  // 0..3

    int blk = blockIdx.x;
    int b = blk / NTRI1;
    int q = blk % NTRI1;
    int i = 0;
    while ((i + 1) * (i + 2) / 2 <= q) i++;
    int j = q - i * (i + 1) / 2;

    const __nv_bfloat16* Xhi = g_xhi + (size_t)b * T * D;
    const __nv_bfloat16* Xlo = g_xlo + (size_t)b * T * D;
    const __nv_bfloat16* srcs[4] = {
        Xhi + (size_t)(i * 128) * D,     // Ahi
        Xlo + (size_t)(i * 128) * D,     // Alo
        Xhi + (size_t)(j * 128) * D,     // Bhi
        Xlo + (size_t)(j * 128) * D      // Blo
    };

    uint32_t pdst[4];
    const __nv_bfloat16* psrc[4];
    #pragma unroll
    for (int uu = 0; uu < 4; uu++) {
        int u = tid + uu * 256;
        int tt = u >> 8, rr = (u >> 1) & 127, hh = u & 1;
        pdst[uu] = tt * TILE32 + ((rr * 32 + hh * 16) ^ ((rr & 4) << 2));
        psrc[uu] = srcs[tt] + (size_t)rr * D + hh * 8;
    }

    uint32_t laneoff = (uint32_t)(((lane & 15) * 32 + (lane >> 4) * 16) ^
                                  (((lane & 15) & 4) << 2));
    uint32_t aoff = (uint32_t)(wm * 64 * 32) + laneoff;
    uint32_t boff = (uint32_t)(wn * 32 * 32) + laneoff;

    float acc[4][4][4];
    #pragma unroll
    for (int am = 0; am < 4; am++)
        #pragma unroll
        for (int an = 0; an < 4; an++)
            #pragma unroll
            for (int c = 0; c < 4; c++) acc[am][an][c] = 0.0f;

    const int NC = D / 16;               // 32 chunks of K=16

    #pragma unroll
    for (int pc = 0; pc < 2; pc++) {
        #pragma unroll
        for (int uu = 0; uu < 4; uu++)
            cp_async16(sbase + pc * STG_B + pdst[uu], psrc[uu] + pc * 16);
        cp_commit();
    }

    for (int c = 0; c < NC; c++) {
        if (c < NC - 1) cp_wait1(); else cp_wait0();
        __syncthreads();
        if (c + 2 < NC) {
            uint32_t stb = sbase + ((c + 2) % 3) * STG_B;
            int k0 = (c + 2) * 16;
            #pragma unroll
            for (int uu = 0; uu < 4; uu++)
                cp_async16(stb + pdst[uu], psrc[uu] + k0);
            cp_commit();
        }

        uint32_t stb = sbase + (c % 3) * STG_B;
        uint32_t bhi[4][2], blo[4][2];
        #pragma unroll
        for (int p = 0; p < 2; p++) {
            uint32_t r[4];
            ldm_x4(r, stb + 2 * TILE32 + boff + p * 512);
            bhi[2 * p][0] = r[0]; bhi[2 * p + 1][0] = r[1];
            bhi[2 * p][1] = r[2]; bhi[2 * p + 1][1] = r[3];
            ldm_x4(r, stb + 3 * TILE32 + boff + p * 512);
            blo[2 * p][0] = r[0]; blo[2 * p + 1][0] = r[1];
            blo[2 * p][1] = r[2]; blo[2 * p + 1][1] = r[3];
        }
        #pragma unroll
        for (int am = 0; am < 4; am++) {
            uint32_t ah[4], al[4];
            ldm_x4(ah, stb + aoff + am * 512);
            ldm_x4(al, stb + TILE32 + aoff + am * 512);
            #pragma unroll
            for (int an = 0; an < 4; an++) {
                mma16816(acc[am][an], ah, bhi[an]);
                mma16816(acc[am][an], ah, blo[an]);
                mma16816(acc[am][an], al, bhi[an]);
            }
        }
    }

    #pragma unroll
    for (int am = 0; am < 4; am++) {
        int row0 = i * 128 + wm * 64 + am * 16 + grp;
        #pragma unroll
        for (int an = 0; an < 4; an++) {
            int col = j * 128 + wn * 32 + an * 8 + tig * 2;
            float* d0 = &g_sim[((size_t)(b * T + row0)) * T + col];
            float* d1 = &g_sim[((size_t)(b * T + row0 + 8)) * T + col];
            *(float2*)d0 = make_float2(acc[am][an][0], acc[am][an][1]);
            *(float2*)d1 = make_float2(acc[am][an][2], acc[am][an][3]);
        }
    }
}

// ---------------- kernel 3: per-row top-k via 2-level radix select -------------
__device__ __forceinline__ void suffix_thresh(const uint32_t* hist, int k,
                                              uint32_t* wsum, int* sh_thr,
                                              int tid, int lane, int wrp) {
    uint32_t h0 = hist[tid];
    uint32_t v = h0;
    #pragma unroll
    for (int off = 1; off < 32; off <<= 1) {
        uint32_t o = __shfl_down_sync(0xffffffffu, v, off);
        if (lane + off < 32) v += o;
    }
    if (lane == 0) wsum[wrp] = v;
    __syncthreads();
    uint32_t exc = 0;
    for (int w2 = wrp + 1; w2 < 8; w2++) exc += wsum[w2];
    uint32_t sfx = v + exc;
    if (sfx >= (uint32_t)k && sfx - h0 < (uint32_t)k) *sh_thr = tid;
    __syncthreads();
}

__global__ void __launch_bounds__(256) topk_kernel(int eff_sim, int eff_con) {
    int row = blockIdx.x;
    int t = row & (T - 1);
    int n = t;
    int tid = threadIdx.x;
    int lane = tid & 31, wrp = tid >> 5;

    __shared__ uint32_t vals[T];
    __shared__ uint32_t hist[256];
    __shared__ uint32_t wsum[8];
    __shared__ unsigned long long wred[8];
    __shared__ uint32_t wred32[8];
    __shared__ int sh_thr;
    __shared__ uint32_t sh_win;
    __shared__ int nsel, nc1, nc2;
    __shared__ int sel[16];
    __shared__ uint16_t cand1[T];
    __shared__ uint32_t cand2[T];

    const float* srow = &g_sim[(size_t)row * T];
    int ksel = min(eff_sim, n);
    if (tid == 0) { nsel = 0; nc1 = 0; nc2 = 0; }
    hist[tid] = 0;
    __syncthreads();

    // pass 1: float4 load + transform + hist
    int n4 = n >> 2;
    for (int s4 = tid; s4 < n4; s4 += 256) {
        float4 f = ((const float4*)srow)[s4];
        uint32_t k0 = fkey(f.x), k1 = fkey(f.y), k2 = fkey(f.z), k3 = fkey(f.w);
        ((uint4*)vals)[s4] = make_uint4(k0, k1, k2, k3);
        if (ksel > 0) {
            atomicAdd(&hist[k0 >> 24], 1u);
            atomicAdd(&hist[k1 >> 24], 1u);
            atomicAdd(&hist[k2 >> 24], 1u);
            atomicAdd(&hist[k3 >> 24], 1u);
        }
    }
    for (int s = n4 * 4 + tid; s < n; s += 256) {
        uint32_t k0 = fkey(srow[s]);
        vals[s] = k0;
        if (ksel > 0) atomicAdd(&hist[k0 >> 24], 1u);
    }
    __syncthreads();

    if (ksel > 0) {
        suffix_thresh(hist, ksel, wsum, &sh_thr, tid, lane, wrp);
        uint32_t b3 = (uint32_t)sh_thr;
        for (int s4 = tid; s4 < n4; s4 += 256) {
            uint4 v = ((const uint4*)vals)[s4];
            int s = s4 * 4;
            uint32_t bb;
            bb = v.x >> 24;
            if (bb > b3) sel[atomicAdd(&nsel, 1) & 15] = s;
            else if (bb == b3) cand1[atomicAdd(&nc1, 1)] = (uint16_t)s;
            bb = v.y >> 24;
            if (bb > b3) sel[atomicAdd(&nsel, 1) & 15] = s + 1;
            else if (bb == b3) cand1[atomicAdd(&nc1, 1)] = (uint16_t)(s + 1);
            bb = v.z >> 24;
            if (bb > b3) sel[atomicAdd(&nsel, 1) & 15] = s + 2;
            else if (bb == b3) cand1[atomicAdd(&nc1, 1)] = (uint16_t)(s + 2);
            bb = v.w >> 24;
            if (bb > b3) sel[atomicAdd(&nsel, 1) & 15] = s + 3;
            else if (bb == b3) cand1[atomicAdd(&nc1, 1)] = (uint16_t)(s + 3);
        }
        for (int s = n4 * 4 + tid; s < n; s += 256) {
            uint32_t bb = vals[s] >> 24;
            if (bb > b3) sel[atomicAdd(&nsel, 1) & 15] = s;
            else if (bb == b3) cand1[atomicAdd(&nc1, 1)] = (uint16_t)s;
        }
        __syncthreads();

        int kneed2 = ksel - nsel;
        if (kneed2 > 0) {
            hist[tid] = 0;
            __syncthreads();
            int m1 = nc1;
            for (int q2 = tid; q2 < m1; q2 += 256)
                atomicAdd(&hist[(vals[cand1[q2]] >> 16) & 0xFFu], 1u);
            __syncthreads();
            suffix_thresh(hist, kneed2, wsum, &sh_thr, tid, lane, wrp);
            uint32_t b2 = (uint32_t)sh_thr;
            for (int q2 = tid; q2 < m1; q2 += 256) {
                int s = cand1[q2];
                uint32_t bb = (vals[s] >> 16) & 0xFFu;
                if (bb > b2) sel[atomicAdd(&nsel, 1) & 15] = s;
                else if (bb == b2)
                    cand2[atomicAdd(&nc2, 1)] =
                        ((vals[s] & 0xFFFFu) << 11) | (uint32_t)(2047 - s);
            }
            __syncthreads();

            int base = nsel;
            int kt = ksel - base;
            int m2 = nc2;
            for (int it = 0; it < kt; it++) {
                uint32_t best = 0;
                for (int q2 = tid; q2 < m2; q2 += 256)
                    best = max(best, cand2[q2]);
                #pragma unroll
                for (int off = 16; off; off >>= 1)
                    best = max(best, __shfl_down_sync(0xffffffffu, best, off));
                if (lane == 0) wred32[wrp] = best;
                __syncthreads();
                if (wrp == 0) {
                    uint32_t bb = (lane < 8) ? wred32[lane] : 0u;
                    #pragma unroll
                    for (int off = 4; off; off >>= 1)
                        bb = max(bb, __shfl_down_sync(0xffffffffu, bb, off));
                    if (lane == 0) sh_win = bb;
                }
                __syncthreads();
                uint32_t wkey = sh_win;
                if (tid == 0 && base + it < 16)
                    sel[base + it] = 2047 - (int)(wkey & 0x7FFu);
                for (int q2 = tid; q2 < m2; q2 += 256)
                    if (cand2[q2] == wkey) cand2[q2] = 0;
                __syncthreads();
            }
            if (tid == 0) nsel = ksel;
        }
    }
    __syncthreads();
    if (tid < ksel) g_top_idx[(size_t)row * 16 + tid] = sel[tid];
    if (tid == 0) g_top_cnt[row] = ksel;

    int m = eff_con - (T - t);
    int mm = 0;
    if (m > 0) {
        mm = min(m, n - ksel);
        if (tid < ksel) vals[sel[tid]] = 0xFFFFFFFFu;
        __syncthreads();
        for (int it = 0; it < mm; it++) {
            unsigned long long best = 0xFFFFFFFFFFFFFFFFull;
            for (int s = tid; s < n; s += 256) {
                unsigned long long key =
                    ((unsigned long long)vals[s] << 32) | (unsigned)s;
                if (key < best) best = key;
            }
            #pragma unroll
            for (int off = 16; off; off >>= 1) {
                unsigned long long o = __shfl_down_sync(0xffffffffu, best, off);
                if (o < best) best = o;
            }
            if (lane == 0) wred[wrp] = best;
            __syncthreads();
            if (wrp == 0) {
                unsigned long long bb =
                    (lane < 8) ? wred[lane] : 0xFFFFFFFFFFFFFFFFull;
                #pragma unroll
                for (int off = 4; off; off >>= 1) {
                    unsigned long long o = __shfl_down_sync(0xffffffffu, bb, off);
                    if (o < bb) bb = o;
                }
                if (lane == 0) {
                    int idx = (int)(unsigned)bb;
                    g_con_idx[(size_t)row * 8 + it] = idx;
                    vals[idx] = 0xFFFFFFFFu;
                }
            }
            __syncthreads();
        }
    }
    if (tid == 0) g_con_cnt[row] = mm;
}

// ---------------- kernel 4: aggregate + blend + GELU + momentum + fused norm ----
__global__ void agg_kernel(const float* __restrict__ hext, int in_buf, int out_buf,
                           const float* __restrict__ gain, const float* __restrict__ bias,
                           const float* __restrict__ lmix, const float* __restrict__ lalpha,
                           const float* __restrict__ lmom, const float* __restrict__ lscale,
                           int r, int final_round, int write_xn,
                           const float* __restrict__ x, float* __restrict__ out) {
    int row = blockIdx.x;
    int b = row >> 11;
    const float* hbase = (in_buf < 0) ? hext : &g_h[in_buf][0];
    const float4* h4 = (const float4*)hbase;

    __shared__ int sidx[16];
    __shared__ int scidx[8];
    __shared__ int scnt[2];
    __shared__ float wnorm[4];
    if (threadIdx.x == 0) { scnt[0] = g_top_cnt[row]; scnt[1] = g_con_cnt[row]; }
    if (threadIdx.x < 16) sidx[threadIdx.x] = g_top_idx[(size_t)row * 16 + threadIdx.x];
    if (threadIdx.x < 8)  scidx[threadIdx.x] = g_con_idx[(size_t)row * 8 + threadIdx.x];
    __syncthreads();
    int cp = scnt[0], cc = scnt[1];

    float mix   = sigmoidf_(lmix[r]);
    float alpha = sigmoidf_(lalpha[r]);
    float mom   = sigmoidf_(lmom[0]);
    float scale = softplusf_(lscale[0]) + 0.01f;
    float invp = 1.0f / fmaxf((float)cp, 1.0f);
    float invc = 1.0f / fmaxf((float)cc, 1.0f);

    int d = threadIdx.x;
    size_t bT = (size_t)b * T;
    const int DQ = D / 4;

    float4 sp = make_float4(0.f, 0.f, 0.f, 0.f);
    float4 sc = make_float4(0.f, 0.f, 0.f, 0.f);
    for (int i = 0; i < cp; i++) {
        float4 v = h4[(bT + sidx[i]) * DQ + d];
        sp.x += v.x; sp.y += v.y; sp.z += v.z; sp.w += v.w;
    }
    for (int i = 0; i < cc; i++) {
        float4 v = h4[(bT + scidx[i]) * DQ + d];
        sc.x += v.x; sc.y += v.y; sc.z += v.z; sc.w += v.w;
    }
    float4 hv = h4[(size_t)row * DQ + d];
    float4 gr = ((const float4*)(gain + (size_t)r * D))[d];
    float4 br = ((const float4*)(bias + (size_t)r * D))[d];

    float hn[4], hvv[4] = {hv.x, hv.y, hv.z, hv.w};
    float spp[4] = {sp.x, sp.y, sp.z, sp.w};
    float scc[4] = {sc.x, sc.y, sc.z, sc.w};
    float grr[4] = {gr.x, gr.y, gr.z, gr.w};
    float brr[4] = {br.x, br.y, br.z, br.w};
    #pragma unroll
    for (int c = 0; c < 4; c++) {
        float ctx = alpha * (spp[c] * invp) + (1.0f - alpha) * (scc[c] * invc);
        float blended = mix * hvv[c] + (1.0f - mix) * ctx;
        float z = blended * grr[c] + brr[c];
        float g = 0.5f * z * (1.0f + erff(z * 0.70710678118654752f));
        hn[c] = mom * hvv[c] + (1.0f - mom) * g;
    }
    float4 ho = make_float4(hn[0], hn[1], hn[2], hn[3]);
    ((float4*)(&g_h[out_buf][0]))[(size_t)row * DQ + d] = ho;
    if (final_round) {
        float4 xv = ((const float4*)x)[(size_t)row * DQ + d];
        float4 ov = make_float4((hn[0] - xv.x) * scale, (hn[1] - xv.y) * scale,
                                (hn[2] - xv.z) * scale, (hn[3] - xv.w) * scale);
        ((float4*)out)[(size_t)row * DQ + d] = ov;
    }
    if (write_xn) {
        float ss = hn[0] * hn[0] + hn[1] * hn[1] + hn[2] * hn[2] + hn[3] * hn[3];
        #pragma unroll
        for (int off = 16; off; off >>= 1)
            ss += __shfl_down_sync(0xffffffffu, ss, off);
        if ((threadIdx.x & 31) == 0) wnorm[threadIdx.x >> 5] = ss;
        __syncthreads();
        float tot = wnorm[0] + wnorm[1] + wnorm[2] + wnorm[3];
        float rinv = 1.0f / fmaxf(sqrtf(tot), 1e-12f);
        __nv_bfloat16 hi[4], lo[4];
        #pragma unroll
        for (int c = 0; c < 4; c++) split_row_elem(hn[c] * rinv, &hi[c], &lo[c]);
        *(uint2*)&g_xhi[(size_t)row * D + d * 4] = *(uint2*)hi;
        *(uint2*)&g_xlo[(size_t)row * D + d * 4] = *(uint2*)lo;
    }
}

// ---------------- launch (kernel launches ONLY; no host API calls) --------------
extern "C" void kernel_launch(void* const* d_in, const int* in_sizes, int n_in,
                              void* d_out, int out_size) {
    const float* x      = (const float*)d_in[0];
    const float* gain   = (const float*)d_in[1];
    const float* bias   = (const float*)d_in[2];
    const float* lmix   = (const float*)d_in[3];
    const float* lalpha = (const float*)d_in[4];
    const float* lmom   = (const float*)d_in[5];
    const float* lscale = (const float*)d_in[6];
    float* out = (float*)d_out;

    static const int KS[3] = {4, 8, 16};
    static const int KC[3] = {2, 4, 8};

    norm_kernel<<<B * T, 128>>>(x);      // round-0 normalize from x
    int inb = -1, outb = 0;
    for (int r = 0; r < 3; r++) {
        sim_mma_kernel<<<B * NTRI1, 256>>>();
        topk_kernel<<<B * T, 256>>>(KS[r], KC[r]);
        agg_kernel<<<B * T, 128>>>(x, inb, outb, gain, bias, lmix, lalpha,
                                   lmom, lscale, r, (r == 2) ? 1 : 0,
                                   (r < 2) ? 1 : 0, x, out);
        inb = outb;
        outb ^= 1;
    }
}

// round 16
// speedup vs baseline: 1.0397x; 1.0157x over previous
#include <cuda_runtime.h>
#include <cuda_bf16.h>
#include <math.h>
#include <float.h>
#include <stdint.h>

#define B 4
#define T 2048
#define D 512
#define NTRI2 272                        // lower-tri 128x64 tiles: sum(2i+2), i<16

// ---------------- scratch (static device memory; no allocation) ----------------
__device__ __nv_bfloat16 g_xhi[(size_t)B * T * D];   // 8 MB
__device__ __nv_bfloat16 g_xlo[(size_t)B * T * D];   // 8 MB
__device__ float g_sim[(size_t)B * T * T];           // 64 MB
__device__ float g_h[2][(size_t)B * T * D];          // 32 MB
__device__ int   g_top_idx[(size_t)B * T * 16];
__device__ int   g_top_cnt[(size_t)B * T];
__device__ int   g_con_idx[(size_t)B * T * 8];
__device__ int   g_con_cnt[(size_t)B * T];

__device__ __forceinline__ float sigmoidf_(float v) { return 1.0f / (1.0f + expf(-v)); }
__device__ __forceinline__ float softplusf_(float v) {
    return (v > 20.0f) ? v : log1pf(expf(v));
}

__device__ __forceinline__ uint32_t smem_u32(const void* p) {
    uint32_t a;
    asm("{ .reg .u64 t; cvta.to.shared.u64 t, %1; cvt.u32.u64 %0, t; }"
        : "=r"(a) : "l"(p));
    return a;
}
__device__ __forceinline__ void cp_async16(uint32_t dst, const void* src) {
    asm volatile("cp.async.cg.shared.global [%0], [%1], 16;"
                 :: "r"(dst), "l"(src) : "memory");
}
__device__ __forceinline__ void cp_commit() {
    asm volatile("cp.async.commit_group;" ::: "memory");
}
__device__ __forceinline__ void cp_wait1() {
    asm volatile("cp.async.wait_group 1;" ::: "memory");
}
__device__ __forceinline__ void cp_wait0() {
    asm volatile("cp.async.wait_group 0;" ::: "memory");
}
__device__ __forceinline__ void mma16816(float* c, const uint32_t* a, const uint32_t* b) {
    asm volatile(
        "mma.sync.aligned.m16n8k16.row.col.f32.bf16.bf16.f32 "
        "{%0,%1,%2,%3}, {%4,%5,%6,%7}, {%8,%9}, {%0,%1,%2,%3};"
        : "+f"(c[0]), "+f"(c[1]), "+f"(c[2]), "+f"(c[3])
        : "r"(a[0]), "r"(a[1]), "r"(a[2]), "r"(a[3]), "r"(b[0]), "r"(b[1]));
}
__device__ __forceinline__ void ldm_x4(uint32_t* r, uint32_t addr) {
    asm volatile("ldmatrix.sync.aligned.m8n8.x4.shared.b16 {%0,%1,%2,%3}, [%4];"
                 : "=r"(r[0]), "=r"(r[1]), "=r"(r[2]), "=r"(r[3]) : "r"(addr));
}

__device__ __forceinline__ void split_row_elem(float v, __nv_bfloat16* hi,
                                               __nv_bfloat16* lo) {
    *hi = __float2bfloat16(v);
    *lo = __float2bfloat16(v - __bfloat162float(*hi));
}

// key transform: monotonic u32 (bigger key == bigger float)
__device__ __forceinline__ uint32_t fkey(float f) {
    unsigned u = __float_as_uint(f);
    return (u & 0x80000000u) ? ~u : (u | 0x80000000u);
}

// ---------------- kernel 1: row-normalize x -> bf16 hi/lo split (round 0 only) --
__global__ void norm_kernel(const float* __restrict__ hext) {
    int row = blockIdx.x;
    const float* h = hext + (size_t)row * D;
    int tid = threadIdx.x;           // 128 threads
    float4 v = ((const float4*)h)[tid];
    float ss = v.x * v.x + v.y * v.y + v.z * v.z + v.w * v.w;
    #pragma unroll
    for (int off = 16; off; off >>= 1) ss += __shfl_down_sync(0xffffffffu, ss, off);
    __shared__ float w[4];
    if ((tid & 31) == 0) w[tid >> 5] = ss;
    __syncthreads();
    float tot = w[0] + w[1] + w[2] + w[3];
    float rinv = 1.0f / fmaxf(sqrtf(tot), 1e-12f);
    float vv[4] = {v.x * rinv, v.y * rinv, v.z * rinv, v.w * rinv};
    __nv_bfloat16 hi[4], lo[4];
    #pragma unroll
    for (int c = 0; c < 4; c++) split_row_elem(vv[c], &hi[c], &lo[c]);
    *(uint2*)&g_xhi[(size_t)row * D + tid * 4] = *(uint2*)hi;
    *(uint2*)&g_xlo[(size_t)row * D + tid * 4] = *(uint2*)lo;
}

// ---------------- kernel 2: sim GEMM 128x64 tiles, 3 CTAs/SM ------------------
// Stage = K=16 slice: Ahi(4K) Alo(4K) Bhi(2K) Blo(2K) = 12 KB; 3 stages = 36 KB.
// XOR-16 swizzle (off ^= (row&4)<<2) keeps cp.async stores + ldmatrix reads
// conflict-free.
#define STG_B 12288

__global__ void __launch_bounds__(256, 3) sim_mma_kernel() {
    __shared__ __align__(128) char smem[3 * STG_B];   // 36 KB static
    uint32_t sbase = smem_u32(smem);
    int tid = threadIdx.x;
    int lane = tid & 31, warp = tid >> 5;
    int wm = warp >> 1;                  // 0..3 (M, 32 rows each)
    int wn = warp & 1;                   // 0..1 (N, 32 cols each)
    int grp = lane >> 2;                 // 0..7
    int tig = lane & 3;                  // 0..3

    int blk = blockIdx.x;
    int b = blk / NTRI2;
    int q = blk % NTRI2;
    int i = 0;                           // 128-row block, q = i*(i+1) + j64
    while ((i + 1) * (i + 2) <= q) i++;
    int j64 = q - i * (i + 1);           // 0 .. 2i+1 (64-col block)

    const __nv_bfloat16* Xhi = g_xhi + (size_t)b * T * D;
    const __nv_bfloat16* Xlo = g_xlo + (size_t)b * T * D;
    const __nv_bfloat16* srcA[2] = {
        Xhi + (size_t)(i * 128) * D,
        Xlo + (size_t)(i * 128) * D
    };
    const __nv_bfloat16* srcB[2] = {
        Xhi + (size_t)(j64 * 64) * D,
        Xlo + (size_t)(j64 * 64) * D
    };

    // producer mapping: 768 16B units per stage, 3 per thread
    uint32_t pdst[3];
    const __nv_bfloat16* psrc[3];
    #pragma unroll
    for (int uu = 0; uu < 3; uu++) {
        int u = tid + uu * 256;
        if (u < 512) {                   // A tiles (128 rows x 2)
            int tt = u >> 8, rr = (u >> 1) & 127, hh = u & 1;
            pdst[uu] = tt * 4096 + ((rr * 32 + hh * 16) ^ ((rr & 4) << 2));
            psrc[uu] = srcA[tt] + (size_t)rr * D + hh * 8;
        } else {                         // B tiles (64 rows x 2)
            int v = u - 512;
            int tt = v >> 7, rr = (v >> 1) & 63, hh = v & 1;
            pdst[uu] = 8192 + tt * 2048 +
                       ((rr * 32 + hh * 16) ^ ((rr & 4) << 2));
            psrc[uu] = srcB[tt] + (size_t)rr * D + hh * 8;
        }
    }

    uint32_t laneoff = (uint32_t)(((lane & 15) * 32 + (lane >> 4) * 16) ^
                                  (((lane & 15) & 4) << 2));
    uint32_t aoff = (uint32_t)(wm * 1024) + laneoff;   // + am*512
    uint32_t boff = (uint32_t)(wn * 1024) + laneoff;   // + p*512

    float acc[2][4][4];
    #pragma unroll
    for (int am = 0; am < 2; am++)
        #pragma unroll
        for (int an = 0; an < 4; an++)
            #pragma unroll
            for (int c = 0; c < 4; c++) acc[am][an][c] = 0.0f;

    const int NC = D / 16;               // 32 chunks of K=16

    #pragma unroll
    for (int pc = 0; pc < 2; pc++) {
        #pragma unroll
        for (int uu = 0; uu < 3; uu++)
            cp_async16(sbase + pc * STG_B + pdst[uu], psrc[uu] + pc * 16);
        cp_commit();
    }

    for (int c = 0; c < NC; c++) {
        if (c < NC - 1) cp_wait1(); else cp_wait0();
        __syncthreads();
        if (c + 2 < NC) {
            uint32_t stb = sbase + ((c + 2) % 3) * STG_B;
            int k0 = (c + 2) * 16;
            #pragma unroll
            for (int uu = 0; uu < 3; uu++)
                cp_async16(stb + pdst[uu], psrc[uu] + k0);
            cp_commit();
        }

        uint32_t stb = sbase + (c % 3) * STG_B;
        uint32_t bhi[4][2], blo[4][2];
        #pragma unroll
        for (int p = 0; p < 2; p++) {
            uint32_t r[4];
            ldm_x4(r, stb + 8192 + boff + p * 512);
            bhi[2 * p][0] = r[0]; bhi[2 * p + 1][0] = r[1];
            bhi[2 * p][1] = r[2]; bhi[2 * p + 1][1] = r[3];
            ldm_x4(r, stb + 10240 + boff + p * 512);
            blo[2 * p][0] = r[0]; blo[2 * p + 1][0] = r[1];
            blo[2 * p][1] = r[2]; blo[2 * p + 1][1] = r[3];
        }
        #pragma unroll
        for (int am = 0; am < 2; am++) {
            uint32_t ah[4], al[4];
            ldm_x4(ah, stb + aoff + am * 512);
            ldm_x4(al, stb + 4096 + aoff + am * 512);
            #pragma unroll
            for (int an = 0; an < 4; an++) {
                mma16816(acc[am][an], ah, bhi[an]);
                mma16816(acc[am][an], ah, blo[an]);
                mma16816(acc[am][an], al, bhi[an]);
            }
        }
    }

    #pragma unroll
    for (int am = 0; am < 2; am++) {
        int row0 = i * 128 + wm * 32 + am * 16 + grp;
        #pragma unroll
        for (int an = 0; an < 4; an++) {
            int col = j64 * 64 + wn * 32 + an * 8 + tig * 2;
            float* d0 = &g_sim[((size_t)(b * T + row0)) * T + col];
            float* d1 = &g_sim[((size_t)(b * T + row0 + 8)) * T + col];
            *(float2*)d0 = make_float2(acc[am][an][0], acc[am][an][1]);
            *(float2*)d1 = make_float2(acc[am][an][2], acc[am][an][3]);
        }
    }
}

// ---------------- kernel 3: per-row top-k via 2-level radix select -------------
__device__ __forceinline__ void suffix_thresh(const uint32_t* hist, int k,
                                              uint32_t* wsum, int* sh_thr,
                                              int tid, int lane, int wrp) {
    uint32_t h0 = hist[tid];
    uint32_t v = h0;
    #pragma unroll
    for (int off = 1; off < 32; off <<= 1) {
        uint32_t o = __shfl_down_sync(0xffffffffu, v, off);
        if (lane + off < 32) v += o;
    }
    if (lane == 0) wsum[wrp] = v;
    __syncthreads();
    uint32_t exc = 0;
    for (int w2 = wrp + 1; w2 < 8; w2++) exc += wsum[w2];
    uint32_t sfx = v + exc;
    if (sfx >= (uint32_t)k && sfx - h0 < (uint32_t)k) *sh_thr = tid;
    __syncthreads();
}

__global__ void __launch_bounds__(256) topk_kernel(int eff_sim, int eff_con) {
    int row = blockIdx.x;
    int t = row & (T - 1);
    int n = t;
    int tid = threadIdx.x;
    int lane = tid & 31, wrp = tid >> 5;

    __shared__ uint32_t vals[T];
    __shared__ uint32_t hist[256];
    __shared__ uint32_t wsum[8];
    __shared__ unsigned long long wred[8];
    __shared__ uint32_t wred32[8];
    __shared__ int sh_thr;
    __shared__ uint32_t sh_win;
    __shared__ int nsel, nc1, nc2;
    __shared__ int sel[16];
    __shared__ uint16_t cand1[T];
    __shared__ uint32_t cand2[T];

    const float* srow = &g_sim[(size_t)row * T];
    int ksel = min(eff_sim, n);
    if (tid == 0) { nsel = 0; nc1 = 0; nc2 = 0; }
    hist[tid] = 0;
    __syncthreads();

    int n4 = n >> 2;
    for (int s4 = tid; s4 < n4; s4 += 256) {
        float4 f = ((const float4*)srow)[s4];
        uint32_t k0 = fkey(f.x), k1 = fkey(f.y), k2 = fkey(f.z), k3 = fkey(f.w);
        ((uint4*)vals)[s4] = make_uint4(k0, k1, k2, k3);
        if (ksel > 0) {
            atomicAdd(&hist[k0 >> 24], 1u);
            atomicAdd(&hist[k1 >> 24], 1u);
            atomicAdd(&hist[k2 >> 24], 1u);
            atomicAdd(&hist[k3 >> 24], 1u);
        }
    }
    for (int s = n4 * 4 + tid; s < n; s += 256) {
        uint32_t k0 = fkey(srow[s]);
        vals[s] = k0;
        if (ksel > 0) atomicAdd(&hist[k0 >> 24], 1u);
    }
    __syncthreads();

    if (ksel > 0) {
        suffix_thresh(hist, ksel, wsum, &sh_thr, tid, lane, wrp);
        uint32_t b3 = (uint32_t)sh_thr;
        for (int s4 = tid; s4 < n4; s4 += 256) {
            uint4 v = ((const uint4*)vals)[s4];
            int s = s4 * 4;
            uint32_t bb;
            bb = v.x >> 24;
            if (bb > b3) sel[atomicAdd(&nsel, 1) & 15] = s;
            else if (bb == b3) cand1[atomicAdd(&nc1, 1)] = (uint16_t)s;
            bb = v.y >> 24;
            if (bb > b3) sel[atomicAdd(&nsel, 1) & 15] = s + 1;
            else if (bb == b3) cand1[atomicAdd(&nc1, 1)] = (uint16_t)(s + 1);
            bb = v.z >> 24;
            if (bb > b3) sel[atomicAdd(&nsel, 1) & 15] = s + 2;
            else if (bb == b3) cand1[atomicAdd(&nc1, 1)] = (uint16_t)(s + 2);
            bb = v.w >> 24;
            if (bb > b3) sel[atomicAdd(&nsel, 1) & 15] = s + 3;
            else if (bb == b3) cand1[atomicAdd(&nc1, 1)] = (uint16_t)(s + 3);
        }
        for (int s = n4 * 4 + tid; s < n; s += 256) {
            uint32_t bb = vals[s] >> 24;
            if (bb > b3) sel[atomicAdd(&nsel, 1) & 15] = s;
            else if (bb == b3) cand1[atomicAdd(&nc1, 1)] = (uint16_t)s;
        }
        __syncthreads();

        int kneed2 = ksel - nsel;
        if (kneed2 > 0) {
            hist[tid] = 0;
            __syncthreads();
            int m1 = nc1;
            for (int q2 = tid; q2 < m1; q2 += 256)
                atomicAdd(&hist[(vals[cand1[q2]] >> 16) & 0xFFu], 1u);
            __syncthreads();
            suffix_thresh(hist, kneed2, wsum, &sh_thr, tid, lane, wrp);
            uint32_t b2 = (uint32_t)sh_thr;
            for (int q2 = tid; q2 < m1; q2 += 256) {
                int s = cand1[q2];
                uint32_t bb = (vals[s] >> 16) & 0xFFu;
                if (bb > b2) sel[atomicAdd(&nsel, 1) & 15] = s;
                else if (bb == b2)
                    cand2[atomicAdd(&nc2, 1)] =
                        ((vals[s] & 0xFFFFu) << 11) | (uint32_t)(2047 - s);
            }
            __syncthreads();

            int base = nsel;
            int kt = ksel - base;
            int m2 = nc2;
            for (int it = 0; it < kt; it++) {
                uint32_t best = 0;
                for (int q2 = tid; q2 < m2; q2 += 256)
                    best = max(best, cand2[q2]);
                #pragma unroll
                for (int off = 16; off; off >>= 1)
                    best = max(best, __shfl_down_sync(0xffffffffu, best, off));
                if (lane == 0) wred32[wrp] = best;
                __syncthreads();
                if (wrp == 0) {
                    uint32_t bb = (lane < 8) ? wred32[lane] : 0u;
                    #pragma unroll
                    for (int off = 4; off; off >>= 1)
                        bb = max(bb, __shfl_down_sync(0xffffffffu, bb, off));
                    if (lane == 0) sh_win = bb;
                }
                __syncthreads();
                uint32_t wkey = sh_win;
                if (tid == 0 && base + it < 16)
                    sel[base + it] = 2047 - (int)(wkey & 0x7FFu);
                for (int q2 = tid; q2 < m2; q2 += 256)
                    if (cand2[q2] == wkey) cand2[q2] = 0;
                __syncthreads();
            }
            if (tid == 0) nsel = ksel;
        }
    }
    __syncthreads();
    if (tid < ksel) g_top_idx[(size_t)row * 16 + tid] = sel[tid];
    if (tid == 0) g_top_cnt[row] = ksel;

    int m = eff_con - (T - t);
    int mm = 0;
    if (m > 0) {
        mm = min(m, n - ksel);
        if (tid < ksel) vals[sel[tid]] = 0xFFFFFFFFu;
        __syncthreads();
        for (int it = 0; it < mm; it++) {
            unsigned long long best = 0xFFFFFFFFFFFFFFFFull;
            for (int s = tid; s < n; s += 256) {
                unsigned long long key =
                    ((unsigned long long)vals[s] << 32) | (unsigned)s;
                if (key < best) best = key;
            }
            #pragma unroll
            for (int off = 16; off; off >>= 1) {
                unsigned long long o = __shfl_down_sync(0xffffffffu, best, off);
                if (o < best) best = o;
            }
            if (lane == 0) wred[wrp] = best;
            __syncthreads();
            if (wrp == 0) {
                unsigned long long bb =
                    (lane < 8) ? wred[lane] : 0xFFFFFFFFFFFFFFFFull;
                #pragma unroll
                for (int off = 4; off; off >>= 1) {
                    unsigned long long o = __shfl_down_sync(0xffffffffu, bb, off);
                    if (o < bb) bb = o;
                }
                if (lane == 0) {
                    int idx = (int)(unsigned)bb;
                    g_con_idx[(size_t)row * 8 + it] = idx;
                    vals[idx] = 0xFFFFFFFFu;
                }
            }
            __syncthreads();
        }
    }
    if (tid == 0) g_con_cnt[row] = mm;
}

// ---------------- kernel 4: aggregate + blend + GELU + momentum + fused norm ----
__global__ void agg_kernel(const float* __restrict__ hext, int in_buf, int out_buf,
                           const float* __restrict__ gain, const float* __restrict__ bias,
                           const float* __restrict__ lmix, const float* __restrict__ lalpha,
                           const float* __restrict__ lmom, const float* __restrict__ lscale,
                           int r, int final_round, int write_xn,
                           const float* __restrict__ x, float* __restrict__ out) {
    int row = blockIdx.x;
    int b = row >> 11;
    const float* hbase = (in_buf < 0) ? hext : &g_h[in_buf][0];
    const float4* h4 = (const float4*)hbase;

    __shared__ int sidx[16];
    __shared__ int scidx[8];
    __shared__ int scnt[2];
    __shared__ float wnorm[4];
    if (threadIdx.x == 0) { scnt[0] = g_top_cnt[row]; scnt[1] = g_con_cnt[row]; }
    if (threadIdx.x < 16) sidx[threadIdx.x] = g_top_idx[(size_t)row * 16 + threadIdx.x];
    if (threadIdx.x < 8)  scidx[threadIdx.x] = g_con_idx[(size_t)row * 8 + threadIdx.x];
    __syncthreads();
    int cp = scnt[0], cc = scnt[1];

    float mix   = sigmoidf_(lmix[r]);
    float alpha = sigmoidf_(lalpha[r]);
    float mom   = sigmoidf_(lmom[0]);
    float scale = softplusf_(lscale[0]) + 0.01f;
    float invp = 1.0f / fmaxf((float)cp, 1.0f);
    float invc = 1.0f / fmaxf((float)cc, 1.0f);

    int d = threadIdx.x;
    size_t bT = (size_t)b * T;
    const int DQ = D / 4;

    float4 sp = make_float4(0.f, 0.f, 0.f, 0.f);
    float4 sc = make_float4(0.f, 0.f, 0.f, 0.f);
    for (int i = 0; i < cp; i++) {
        float4 v = h4[(bT + sidx[i]) * DQ + d];
        sp.x += v.x; sp.y += v.y; sp.z += v.z; sp.w += v.w;
    }
    for (int i = 0; i < cc; i++) {
        float4 v = h4[(bT + scidx[i]) * DQ + d];
        sc.x += v.x; sc.y += v.y; sc.z += v.z; sc.w += v.w;
    }
    float4 hv = h4[(size_t)row * DQ + d];
    float4 gr = ((const float4*)(gain + (size_t)r * D))[d];
    float4 br = ((const float4*)(bias + (size_t)r * D))[d];

    float hn[4], hvv[4] = {hv.x, hv.y, hv.z, hv.w};
    float spp[4] = {sp.x, sp.y, sp.z, sp.w};
    float scc[4] = {sc.x, sc.y, sc.z, sc.w};
    float grr[4] = {gr.x, gr.y, gr.z, gr.w};
    float brr[4] = {br.x, br.y, br.z, br.w};
    #pragma unroll
    for (int c = 0; c < 4; c++) {
        float ctx = alpha * (spp[c] * invp) + (1.0f - alpha) * (scc[c] * invc);
        float blended = mix * hvv[c] + (1.0f - mix) * ctx;
        float z = blended * grr[c] + brr[c];
        float g = 0.5f * z * (1.0f + erff(z * 0.70710678118654752f));
        hn[c] = mom * hvv[c] + (1.0f - mom) * g;
    }
    float4 ho = make_float4(hn[0], hn[1], hn[2], hn[3]);
    ((float4*)(&g_h[out_buf][0]))[(size_t)row * DQ + d] = ho;
    if (final_round) {
        float4 xv = ((const float4*)x)[(size_t)row * DQ + d];
        float4 ov = make_float4((hn[0] - xv.x) * scale, (hn[1] - xv.y) * scale,
                                (hn[2] - xv.z) * scale, (hn[3] - xv.w) * scale);
        ((float4*)out)[(size_t)row * DQ + d] = ov;
    }
    if (write_xn) {
        float ss = hn[0] * hn[0] + hn[1] * hn[1] + hn[2] * hn[2] + hn[3] * hn[3];
        #pragma unroll
        for (int off = 16; off; off >>= 1)
            ss += __shfl_down_sync(0xffffffffu, ss, off);
        if ((threadIdx.x & 31) == 0) wnorm[threadIdx.x >> 5] = ss;
        __syncthreads();
        float tot = wnorm[0] + wnorm[1] + wnorm[2] + wnorm[3];
        float rinv = 1.0f / fmaxf(sqrtf(tot), 1e-12f);
        __nv_bfloat16 hi[4], lo[4];
        #pragma unroll
        for (int c = 0; c < 4; c++) split_row_elem(hn[c] * rinv, &hi[c], &lo[c]);
        *(uint2*)&g_xhi[(size_t)row * D + d * 4] = *(uint2*)hi;
        *(uint2*)&g_xlo[(size_t)row * D + d * 4] = *(uint2*)lo;
    }
}

// ---------------- launch (kernel launches ONLY; no host API calls) --------------
extern "C" void kernel_launch(void* const* d_in, const int* in_sizes, int n_in,
                              void* d_out, int out_size) {
    const float* x      = (const float*)d_in[0];
    const float* gain   = (const float*)d_in[1];
    const float* bias   = (const float*)d_in[2];
    const float* lmix   = (const float*)d_in[3];
    const float* lalpha = (const float*)d_in[4];
    const float* lmom   = (const float*)d_in[5];
    const float* lscale = (const float*)d_in[6];
    float* out = (float*)d_out;

    static const int KS[3] = {4, 8, 16};
    static const int KC[3] = {2, 4, 8};

    norm_kernel<<<B * T, 128>>>(x);      // round-0 normalize from x
    int inb = -1, outb = 0;
    for (int r = 0; r < 3; r++) {
        sim_mma_kernel<<<B * NTRI2, 256>>>();
        topk_kernel<<<B * T, 256>>>(KS[r], KC[r]);
        agg_kernel<<<B * T, 128>>>(x, inb, outb, gain, bias, lmix, lalpha,
                                   lmom, lscale, r, (r == 2) ? 1 : 0,
                                   (r < 2) ? 1 : 0, x, out);
        inb = outb;
        outb ^= 1;
    }
}